// round 1
// baseline (speedup 1.0000x reference)
#include <cuda_runtime.h>
#include <math.h>

#define NTOK 8192
#define NE   16384
#define CDIM 256
#define HW   1024
#define ZQ_ELEMS (NTOK*CDIM)   // 2097152
#define EPSF 1e-6f
#define NSPLIT 8

// ---- device scratch (static: allocation-free) ----
__device__ float g_emb[NE * CDIM];                 // 16 MB: codebook @ W^T
__device__ float g_e2[NE];                         // |emb_j|^2
__device__ unsigned long long g_best[NTOK];        // packed (scorekey<<32)|idx

// monotone float -> uint key (smaller float => smaller key)
__device__ __forceinline__ unsigned int fkey(float f) {
    unsigned int u = __float_as_uint(f);
    return (u & 0x80000000u) ? ~u : (u | 0x80000000u);
}

__global__ void init_kernel(float* out, int out_size) {
    int i = blockIdx.x * blockDim.x + threadIdx.x;
    if (i < NE)   g_e2[i] = 0.0f;
    if (i < NTOK) g_best[i] = 0xFFFFFFFFFFFFFFFFULL;
    if (i == 0 && out_size > ZQ_ELEMS) out[ZQ_ELEMS] = 0.0f;  // loss accumulator
}

// ---------------------------------------------------------------------------
// emb = codebook @ W^T  (16384 x 256 x 256), also accumulates e2 = rowwise |emb|^2
// Tile: 64 codes x 64 channels, K-chunks of 16, 256 threads, 4x4 micro-tile.
// ---------------------------------------------------------------------------
__global__ __launch_bounds__(256) void emb_kernel(const float* __restrict__ cb,
                                                  const float* __restrict__ W) {
    __shared__ float As[16][68];   // As[k][code]   (pad 68 => 16B-aligned rows)
    __shared__ float Bs[16][68];   // Bs[k][chan]
    const int t  = threadIdx.x;
    const int tx = t & 15, ty = t >> 4;
    const int m0 = blockIdx.y * 64;   // code tile
    const int n0 = blockIdx.x * 64;   // channel tile

    float acc[4][4] = {};
    for (int k0 = 0; k0 < CDIM; k0 += 16) {
        __syncthreads();
        const int kk = t & 15, mm = t >> 4;
        #pragma unroll
        for (int r = 0; r < 4; r++) {
            As[kk][mm + 16*r] = cb[(m0 + mm + 16*r) * CDIM + k0 + kk];
            Bs[kk][mm + 16*r] = W [(n0 + mm + 16*r) * CDIM + k0 + kk];
        }
        __syncthreads();
        #pragma unroll
        for (int k = 0; k < 16; k++) {
            float4 a = *(const float4*)&As[k][ty * 4];
            float4 b = *(const float4*)&Bs[k][tx * 4];
            float av[4] = {a.x, a.y, a.z, a.w};
            float bv[4] = {b.x, b.y, b.z, b.w};
            #pragma unroll
            for (int i = 0; i < 4; i++)
                #pragma unroll
                for (int j = 0; j < 4; j++)
                    acc[i][j] = fmaf(av[i], bv[j], acc[i][j]);
        }
    }
    #pragma unroll
    for (int i = 0; i < 4; i++) {
        const int code = m0 + ty * 4 + i;
        float4 v = make_float4(acc[i][0], acc[i][1], acc[i][2], acc[i][3]);
        *(float4*)&g_emb[(size_t)code * CDIM + n0 + tx * 4] = v;
        float e2p = v.x*v.x + v.y*v.y + v.z*v.z + v.w*v.w;
        atomicAdd(&g_e2[code], e2p);
    }
}

// ---------------------------------------------------------------------------
// Fused distance GEMM + argmin.
// score(t, j) = |e_j|^2 - 2 * z_t . e_j   (dropping |z_t|^2: argmin-invariant)
// Grid: (NSPLIT code splits, 128 token tiles of 64). Per block: 64 tok x
// (NE/NSPLIT) codes, K=256 chunked by 16, 4x4 register micro-tile.
// z is (b,c,h,w): z_flat[t][k] = z[b*262144 + k*1024 + hw], t = b*1024+hw,
// so a 64-token tile is 64 *contiguous* floats per k => coalesced loads.
// ---------------------------------------------------------------------------
__global__ __launch_bounds__(256) void dist_kernel(const float* __restrict__ z) {
    __shared__ float Zs[16][68];
    __shared__ float Es[16][68];
    const int t  = threadIdx.x;
    const int tx = t & 15, ty = t >> 4;
    const int m0  = blockIdx.y * 64;
    const int bb  = m0 >> 10;
    const int hw0 = m0 & (HW - 1);
    const float* zb = z + (size_t)bb * CDIM * HW + hw0;

    unsigned long long best[4] = {~0ULL, ~0ULL, ~0ULL, ~0ULL};
    const int nbase = blockIdx.x * (NE / NSPLIT);

    for (int ntile = 0; ntile < NE / NSPLIT; ntile += 64) {
        const int n0 = nbase + ntile;
        float acc[4][4] = {};
        for (int k0 = 0; k0 < CDIM; k0 += 16) {
            __syncthreads();
            {
                const int mz = t & 63, kz = t >> 6;
                #pragma unroll
                for (int r = 0; r < 4; r++)
                    Zs[kz + 4*r][mz] = zb[(size_t)(k0 + kz + 4*r) * HW + mz];
                const int ke = t & 15, ne = t >> 4;
                #pragma unroll
                for (int r = 0; r < 4; r++)
                    Es[ke][ne + 16*r] = g_emb[(size_t)(n0 + ne + 16*r) * CDIM + k0 + ke];
            }
            __syncthreads();
            #pragma unroll
            for (int k = 0; k < 16; k++) {
                float4 a = *(const float4*)&Zs[k][ty * 4];
                float4 b = *(const float4*)&Es[k][tx * 4];
                float av[4] = {a.x, a.y, a.z, a.w};
                float bv[4] = {b.x, b.y, b.z, b.w};
                #pragma unroll
                for (int i = 0; i < 4; i++)
                    #pragma unroll
                    for (int j = 0; j < 4; j++)
                        acc[i][j] = fmaf(av[i], bv[j], acc[i][j]);
            }
        }
        // argmin epilogue for this 64-code tile
        #pragma unroll
        for (int j = 0; j < 4; j++) {
            const int code = n0 + tx * 4 + j;
            const float e2 = g_e2[code];
            #pragma unroll
            for (int i = 0; i < 4; i++) {
                float s = fmaf(-2.0f, acc[i][j], e2);
                unsigned long long key =
                    ((unsigned long long)fkey(s) << 32) | (unsigned int)code;
                if (key < best[i]) best[i] = key;
            }
        }
    }
    // reduce over the 16 lanes (same ty = same tokens; contiguous half-warp)
    #pragma unroll
    for (int i = 0; i < 4; i++) {
        unsigned long long v = best[i];
        #pragma unroll
        for (int off = 8; off > 0; off >>= 1) {
            unsigned long long o = __shfl_xor_sync(0xFFFFFFFFu, v, off);
            if (o < v) v = o;
        }
        if (tx == 0) atomicMin(&g_best[m0 + ty * 4 + i], v);
    }
}

// ---------------------------------------------------------------------------
// Rotation trick (forward values only) + loss + indices.
// rot = z - 2(z.w)w + 2(z.u)q, scaled by |e|/(|z|+eps); closed-form from
// three reductions: ZZ=|z|^2, ZE=z.e, EE=|e|^2.
// ---------------------------------------------------------------------------
__global__ __launch_bounds__(256) void rotate_kernel(const float* __restrict__ z,
                                                     float* __restrict__ out,
                                                     int out_size) {
    const int tok = blockIdx.x;
    const int ch  = threadIdx.x;
    const int bb  = tok >> 10;
    const int hw  = tok & (HW - 1);
    const unsigned int idx = (unsigned int)(g_best[tok] & 0xFFFFFFFFULL);

    const size_t zoff = (size_t)bb * CDIM * HW + (size_t)ch * HW + hw;
    const float zc = z[zoff];
    const float ec = g_emb[(size_t)idx * CDIM + ch];

    float zz = zc * zc, ze = zc * ec, ee = ec * ec;
    #pragma unroll
    for (int off = 16; off > 0; off >>= 1) {
        zz += __shfl_xor_sync(0xFFFFFFFFu, zz, off);
        ze += __shfl_xor_sync(0xFFFFFFFFu, ze, off);
        ee += __shfl_xor_sync(0xFFFFFFFFu, ee, off);
    }
    __shared__ float s_zz[8], s_ze[8], s_ee[8];
    const int warp = ch >> 5, lane = ch & 31;
    if (lane == 0) { s_zz[warp] = zz; s_ze[warp] = ze; s_ee[warp] = ee; }
    __syncthreads();
    float ZZ = 0.f, ZE = 0.f, EE = 0.f;
    #pragma unroll
    for (int i = 0; i < 8; i++) { ZZ += s_zz[i]; ZE += s_ze[i]; EE += s_ee[i]; }

    const float ns = sqrtf(ZZ), nt = sqrtf(EE);
    const float dns = ns + EPSF, dnt = nt + EPSF;
    const float rdns = 1.0f / dns, rdnt = 1.0f / dnt;
    const float uq2 = ZZ*rdns*rdns + 2.0f*ZE*rdns*rdnt + EE*rdnt*rdnt;
    const float rdnw = 1.0f / (sqrtf(uq2) + EPSF);
    const float sw = (ZZ * rdns + ZE * rdnt) * rdnw;   // src . w_
    const float su = ZZ * rdns;                        // src . u
    const float scale = nt * rdns;

    const float u_ch = zc * rdns, q_ch = ec * rdnt;
    const float w_ch = (u_ch + q_ch) * rdnw;
    const float rot = zc - 2.0f * sw * w_ch + 2.0f * su * q_ch;
    out[zoff] = rot * scale;

    if (ch == 0) {
        if (out_size > ZQ_ELEMS) {
            // loss = COMMIT_W * (1 + BETA) * mean((z - zq)^2) = 1.25 * mse
            const float sq = ZZ - 2.0f * ZE + EE;      // sum over channels of (z-e)^2
            atomicAdd(&out[ZQ_ELEMS], 1.25f * sq / (float)ZQ_ELEMS);
        }
        if (out_size >= ZQ_ELEMS + 1 + NTOK)
            out[ZQ_ELEMS + 1 + tok] = (float)idx;
    }
}

extern "C" void kernel_launch(void* const* d_in, const int* in_sizes, int n_in,
                              void* d_out, int out_size) {
    const float* z  = (const float*)d_in[0];   // (8,256,32,32)
    const float* cb = (const float*)d_in[1];   // (16384,256)
    const float* W  = (const float*)d_in[2];   // (256,256)
    float* out = (float*)d_out;

    init_kernel<<<64, 256>>>(out, out_size);
    emb_kernel<<<dim3(4, NE / 64), 256>>>(cb, W);
    dist_kernel<<<dim3(NSPLIT, NTOK / 64), 256>>>(z);
    rotate_kernel<<<NTOK, 256>>>(z, out, out_size);
}

// round 3
// speedup vs baseline: 2.0552x; 2.0552x over previous
#include <cuda_runtime.h>
#include <cuda_bf16.h>
#include <cstdint>
#include <math.h>

#define NTOK 8192
#define NE   16384
#define CDIM 256
#define HW   1024
#define ZQ_ELEMS (NTOK*CDIM)
#define EPSF 1e-6f

#define NSPLIT2 2
#define MTILE 128          // tokens per CTA
#define NTILE 128          // codes per N-tile
#define NT_PER_CTA ((NE/NSPLIT2)/NTILE)   // 64 tiles
#define NCHUNK (NT_PER_CTA*4)             // 256 64-k chunks

// smem layout (dist kernel)
#define BROW 288u          // 64k * 4B (hi/lo pairs) + 32B pad  (≡32 mod 128 -> CF lds.64)
#define AROW 1056u         // 256k * 4B + 32B pad
#define OFF_B(buf) ((unsigned)(buf)*36864u)      // 128 * 288
#define OFF_E2 73728u                            // 2 * 512B
#define OFF_A  74752u
#define SMEM_DYN_D (74752 + 128*1056)            // 209920 B

// ---------------- device scratch (static, allocation-free) ----------------
__device__ float g_emb[NE * CDIM];        // fp32 emb = cb @ W^T (refine/rotate)
__device__ float g_e2[NE];                // |emb_j|^2
__device__ uint2 g_emb_hl[NE * CDIM/2];   // interleaved bf16 pairs (hi2,lo2)
__device__ uint2 g_z_hl[NTOK * CDIM/2];   // interleaved bf16 pairs for z
__device__ unsigned long long g_cand[NTOK * 4];  // best-2 per (tok, split)

// ---------------- helpers --------------------------------------------------
__device__ __forceinline__ uint32_t smem_u32(const void* p) {
    uint32_t a;
    asm("{ .reg .u64 t; cvta.to.shared.u64 t, %1; cvt.u32.u64 %0, t; }"
        : "=r"(a) : "l"(p));
    return a;
}
__device__ __forceinline__ void cp16(uint32_t dst, const void* src) {
    asm volatile("cp.async.cg.shared.global [%0], [%1], 16;" :: "r"(dst), "l"(src));
}
__device__ __forceinline__ void cp_commit() {
    asm volatile("cp.async.commit_group;");
}
__device__ __forceinline__ void cp_wait0() {
    asm volatile("cp.async.wait_group 0;");
}
__device__ __forceinline__ void lds64(uint32_t& x, uint32_t& y, uint32_t a) {
    asm volatile("ld.shared.v2.u32 {%0,%1}, [%2];" : "=r"(x), "=r"(y) : "r"(a));
}
__device__ __forceinline__ void mma16816(float* c, const uint32_t* a,
                                         uint32_t b0, uint32_t b1) {
    asm volatile(
        "mma.sync.aligned.m16n8k16.row.col.f32.bf16.bf16.f32 "
        "{%0,%1,%2,%3}, {%4,%5,%6,%7}, {%8,%9}, {%0,%1,%2,%3};"
        : "+f"(c[0]), "+f"(c[1]), "+f"(c[2]), "+f"(c[3])
        : "r"(a[0]), "r"(a[1]), "r"(a[2]), "r"(a[3]), "r"(b0), "r"(b1));
}
// monotone float -> uint key (smaller float => smaller key)
__device__ __forceinline__ unsigned int fkey(float f) {
    unsigned int u = __float_as_uint(f);
    return (u & 0x80000000u) ? ~u : (u | 0x80000000u);
}
__device__ __forceinline__ unsigned short bfu(__nv_bfloat16 h) {
    return __bfloat16_as_ushort(h);
}
__device__ __forceinline__ void best2_upd(unsigned long long& b1,
                                          unsigned long long& b2,
                                          unsigned long long k) {
    if (k < b1) { b2 = b1; b1 = k; } else if (k < b2) { b2 = k; }
}

// ---------------------------------------------------------------------------
// z split: fp32 z -> interleaved bf16 hi/lo pairs, token-major rows.
// block: 64 tokens x 32 kpairs; grid (4 kpair-blocks, 128 token-blocks)
// ---------------------------------------------------------------------------
__global__ __launch_bounds__(256) void zsplit_kernel(const float* __restrict__ z) {
    __shared__ float s[64][65];
    const int tid = threadIdx.x;
    const int t0 = blockIdx.y * 64;
    const int p0 = blockIdx.x * 32;
    const int bb = t0 >> 10;
    const int hw0 = t0 & (HW - 1);
    const float* zb = z + (size_t)bb * CDIM * HW + hw0;

    #pragma unroll
    for (int r = 0; r < 16; r++) {
        const int id = tid + 256 * r;
        const int kk = id >> 6, tt = id & 63;
        s[kk][tt] = zb[(size_t)(2 * p0 + kk) * HW + tt];
    }
    __syncthreads();
    #pragma unroll
    for (int r = 0; r < 8; r++) {
        const int id = tid + 256 * r;
        const int tt = id >> 5, pp = id & 31;
        const float z0 = s[2 * pp][tt], z1 = s[2 * pp + 1][tt];
        const __nv_bfloat16 h0 = __float2bfloat16(z0), h1 = __float2bfloat16(z1);
        const __nv_bfloat16 l0 = __float2bfloat16(z0 - __bfloat162float(h0));
        const __nv_bfloat16 l1 = __float2bfloat16(z1 - __bfloat162float(h1));
        uint2 v;
        v.x = (uint32_t)bfu(h0) | ((uint32_t)bfu(h1) << 16);
        v.y = (uint32_t)bfu(l0) | ((uint32_t)bfu(l1) << 16);
        g_z_hl[(size_t)(t0 + tt) * 128 + p0 + pp] = v;
    }
}

// ---------------------------------------------------------------------------
// emb = codebook @ W^T fp32 + interleaved bf16 hi/lo pair output
// ---------------------------------------------------------------------------
__global__ __launch_bounds__(256) void emb_kernel(const float* __restrict__ cb,
                                                  const float* __restrict__ W) {
    __shared__ float As[16][68];
    __shared__ float Bs[16][68];
    const int t  = threadIdx.x;
    const int tx = t & 15, ty = t >> 4;
    const int m0 = blockIdx.y * 64;
    const int n0 = blockIdx.x * 64;

    float acc[4][4] = {};
    for (int k0 = 0; k0 < CDIM; k0 += 16) {
        __syncthreads();
        const int kk = t & 15, mm = t >> 4;
        #pragma unroll
        for (int r = 0; r < 4; r++) {
            As[kk][mm + 16*r] = cb[(m0 + mm + 16*r) * CDIM + k0 + kk];
            Bs[kk][mm + 16*r] = W [(n0 + mm + 16*r) * CDIM + k0 + kk];
        }
        __syncthreads();
        #pragma unroll
        for (int k = 0; k < 16; k++) {
            float4 a = *(const float4*)&As[k][ty * 4];
            float4 b = *(const float4*)&Bs[k][tx * 4];
            float av[4] = {a.x, a.y, a.z, a.w};
            float bv[4] = {b.x, b.y, b.z, b.w};
            #pragma unroll
            for (int i = 0; i < 4; i++)
                #pragma unroll
                for (int j = 0; j < 4; j++)
                    acc[i][j] = fmaf(av[i], bv[j], acc[i][j]);
        }
    }
    #pragma unroll
    for (int i = 0; i < 4; i++) {
        const int code = m0 + ty * 4 + i;
        float4 v = make_float4(acc[i][0], acc[i][1], acc[i][2], acc[i][3]);
        const int e0 = code * CDIM + n0 + tx * 4;
        *(float4*)&g_emb[e0] = v;
        __nv_bfloat16 h0 = __float2bfloat16(v.x), h1 = __float2bfloat16(v.y);
        __nv_bfloat16 h2 = __float2bfloat16(v.z), h3 = __float2bfloat16(v.w);
        __nv_bfloat16 l0 = __float2bfloat16(v.x - __bfloat162float(h0));
        __nv_bfloat16 l1 = __float2bfloat16(v.y - __bfloat162float(h1));
        __nv_bfloat16 l2 = __float2bfloat16(v.z - __bfloat162float(h2));
        __nv_bfloat16 l3 = __float2bfloat16(v.w - __bfloat162float(h3));
        uint4 p;
        p.x = (uint32_t)bfu(h0) | ((uint32_t)bfu(h1) << 16);
        p.y = (uint32_t)bfu(l0) | ((uint32_t)bfu(l1) << 16);
        p.z = (uint32_t)bfu(h2) | ((uint32_t)bfu(h3) << 16);
        p.w = (uint32_t)bfu(l2) | ((uint32_t)bfu(l3) << 16);
        ((uint4*)g_emb_hl)[code * 64 + (n0 + tx * 4) / 4] = p;
    }
}

// deterministic e2 + loss-slot init
__global__ __launch_bounds__(256) void e2_kernel(float* out, int out_size) {
    const int code = blockIdx.x * 8 + (threadIdx.x >> 5);
    const int lane = threadIdx.x & 31;
    const float* row = g_emb + (size_t)code * CDIM;
    float s = 0.0f;
    #pragma unroll
    for (int i = 0; i < 8; i++) { float v = row[lane + 32*i]; s = fmaf(v, v, s); }
    #pragma unroll
    for (int off = 16; off > 0; off >>= 1) s += __shfl_xor_sync(0xFFFFFFFFu, s, off);
    if (lane == 0) g_e2[code] = s;
    if (blockIdx.x == 0 && threadIdx.x == 0 && out_size > ZQ_ELEMS) out[ZQ_ELEMS] = 0.0f;
}

// ---------------------------------------------------------------------------
// Distance GEMM (split-bf16 3-pass via HMMA.16816) + best-2 per (token,split).
// CTA tile 128x128, 8 warps = 4(M) x 2(N), warp tile 32x64.
// score(t,j) = |e_j|^2 - 2 z_t.e_j ; accs hold z.e (hi*hi + lo*hi + hi*lo).
// ---------------------------------------------------------------------------
__global__ __launch_bounds__(256, 1) void dist_kernel(float* dummy) {
    extern __shared__ char smem[];
    const uint32_t sb = smem_u32(smem);
    const int tid  = threadIdx.x;
    const int lane = tid & 31, wid = tid >> 5;
    const int gid  = lane >> 2, tig = lane & 3;
    const int wm = wid & 3, wn = wid >> 2;
    const int m_base = wm * 32, n_base = wn * 64;
    const int m0 = blockIdx.y * MTILE;
    const int nbase = blockIdx.x * (NE / NSPLIT2);

    // ---- prologue staging: A (full K) + chunk 0 + e2 tile 0 ----
    #pragma unroll 4
    for (int r = 0; r < 32; r++) {
        const int i = tid + 256 * r;
        const int ml = i >> 6, cj = i & 63;
        cp16(sb + OFF_A + (unsigned)ml * AROW + (unsigned)cj * 16u,
             g_z_hl + (size_t)(m0 + ml) * 128 + cj * 2);
    }
    #pragma unroll
    for (int r = 0; r < 8; r++) {
        const int i = tid + 256 * r;
        const int nl = i >> 4, cj = i & 15;
        cp16(sb + OFF_B(0) + (unsigned)nl * BROW + (unsigned)cj * 16u,
             g_emb_hl + (size_t)(nbase + nl) * 128 + cj * 2);
    }
    if (tid < 32)
        cp16(sb + OFF_E2 + (unsigned)tid * 16u, g_e2 + nbase + tid * 4);
    cp_commit();
    cp_wait0();
    __syncthreads();

    unsigned long long b1[4] = {~0ULL, ~0ULL, ~0ULL, ~0ULL};
    unsigned long long b2[4] = {~0ULL, ~0ULL, ~0ULL, ~0ULL};

    int q = 0;
    for (int nt = 0; nt < NT_PER_CTA; nt++) {
        float acc[2][8][4] = {};
        #pragma unroll 1
        for (int kc = 0; kc < 4; kc++, q++) {
            // prefetch next chunk
            const int qn = q + 1;
            if (qn < NCHUNK) {
                const int nt2 = qn >> 2, kc2 = qn & 3;
                const int n2 = nbase + nt2 * NTILE;
                #pragma unroll
                for (int r = 0; r < 8; r++) {
                    const int i = tid + 256 * r;
                    const int nl = i >> 4, cj = i & 15;
                    cp16(sb + OFF_B(qn & 1) + (unsigned)nl * BROW + (unsigned)cj * 16u,
                         g_emb_hl + (size_t)(n2 + nl) * 128 + kc2 * 32 + cj * 2);
                }
                if (kc2 == 0 && tid < 32)
                    cp16(sb + OFF_E2 + ((unsigned)(nt2 & 1)) * 512u + (unsigned)tid * 16u,
                         g_e2 + n2 + tid * 4);
            }
            cp_commit();

            const uint32_t Bb = sb + OFF_B(q & 1);
            const uint32_t Ab = sb + OFF_A;
            #pragma unroll
            for (int s = 0; s < 4; s++) {
                // A fragments: hi and lo together (interleaved pairs)
                uint32_t ah[2][4], al[2][4];
                #pragma unroll
                for (int ma = 0; ma < 2; ma++) {
                    const uint32_t abase = Ab
                        + (uint32_t)(m_base + ma * 16 + gid) * AROW
                        + (uint32_t)(kc * 32 + s * 8 + tig) * 8u;
                    lds64(ah[ma][0], al[ma][0], abase);
                    lds64(ah[ma][1], al[ma][1], abase + 8u * AROW);
                    lds64(ah[ma][2], al[ma][2], abase + 32u);
                    lds64(ah[ma][3], al[ma][3], abase + 8u * AROW + 32u);
                }
                #pragma unroll
                for (int na = 0; na < 8; na++) {
                    const uint32_t bbase = Bb
                        + (uint32_t)(n_base + na * 8 + gid) * BROW
                        + (uint32_t)(s * 8 + tig) * 8u;
                    uint32_t bh0, bl0, bh1, bl1;
                    lds64(bh0, bl0, bbase);
                    lds64(bh1, bl1, bbase + 32u);
                    #pragma unroll
                    for (int ma = 0; ma < 2; ma++) {
                        mma16816(acc[ma][na], ah[ma], bh0, bh1);  // zh*eh
                        mma16816(acc[ma][na], al[ma], bh0, bh1);  // zl*eh
                        mma16816(acc[ma][na], ah[ma], bl0, bl1);  // zh*el
                    }
                }
            }
            cp_wait0();
            __syncthreads();
        }
        // ---- epilogue: scores + best-2 ----
        const float* e2p = (const float*)(smem + OFF_E2 + (size_t)(nt & 1) * 512);
        const int n0 = nbase + nt * NTILE;
        #pragma unroll
        for (int na = 0; na < 8; na++) {
            const int c0 = n_base + na * 8 + tig * 2;
            const float e2a = e2p[c0], e2b = e2p[c0 + 1];
            #pragma unroll
            for (int ma = 0; ma < 2; ma++) {
                const float s00 = fmaf(-2.0f, acc[ma][na][0], e2a);
                const float s01 = fmaf(-2.0f, acc[ma][na][1], e2b);
                const float s10 = fmaf(-2.0f, acc[ma][na][2], e2a);
                const float s11 = fmaf(-2.0f, acc[ma][na][3], e2b);
                const int q0 = ma * 2;
                best2_upd(b1[q0], b2[q0],
                    ((unsigned long long)fkey(s00) << 32) | (unsigned)(n0 + c0));
                best2_upd(b1[q0], b2[q0],
                    ((unsigned long long)fkey(s01) << 32) | (unsigned)(n0 + c0 + 1));
                best2_upd(b1[q0 + 1], b2[q0 + 1],
                    ((unsigned long long)fkey(s10) << 32) | (unsigned)(n0 + c0));
                best2_upd(b1[q0 + 1], b2[q0 + 1],
                    ((unsigned long long)fkey(s11) << 32) | (unsigned)(n0 + c0 + 1));
            }
        }
    }

    // ---- CTA reduction ----
    __syncthreads();
    unsigned long long* red = (unsigned long long*)smem;  // 128 rows x 2 wn x 2
    #pragma unroll
    for (int qq = 0; qq < 4; qq++) {
        unsigned long long k1 = b1[qq], k2 = b2[qq];
        #pragma unroll
        for (int off = 1; off <= 2; off <<= 1) {
            unsigned long long o1 = __shfl_xor_sync(0xFFFFFFFFu, k1, off);
            unsigned long long o2 = __shfl_xor_sync(0xFFFFFFFFu, k2, off);
            unsigned long long n1 = k1 < o1 ? k1 : o1;
            unsigned long long hi = k1 < o1 ? o1 : k1;
            unsigned long long lo2 = k2 < o2 ? k2 : o2;
            k1 = n1;
            k2 = hi < lo2 ? hi : lo2;
        }
        if (tig == 0) {
            const int row = m_base + (qq >> 1) * 16 + gid + (qq & 1) * 8;
            red[(row * 2 + wn) * 2 + 0] = k1;
            red[(row * 2 + wn) * 2 + 1] = k2;
        }
    }
    __syncthreads();
    if (tid < 128) {
        unsigned long long a1 = red[tid * 4 + 0], a2 = red[tid * 4 + 1];
        unsigned long long c1 = red[tid * 4 + 2], c2 = red[tid * 4 + 3];
        unsigned long long k1 = a1 < c1 ? a1 : c1;
        unsigned long long hi = a1 < c1 ? c1 : a1;
        unsigned long long lo2 = a2 < c2 ? a2 : c2;
        unsigned long long k2 = hi < lo2 ? hi : lo2;
        g_cand[(size_t)(m0 + tid) * 4 + blockIdx.x * 2 + 0] = k1;
        g_cand[(size_t)(m0 + tid) * 4 + blockIdx.x * 2 + 1] = k2;
    }
}

// ---------------------------------------------------------------------------
// Candidate refine (exact fp32) + rotation trick + loss + indices.
// ---------------------------------------------------------------------------
__global__ __launch_bounds__(256) void rotate_kernel(const float* __restrict__ z,
                                                     float* __restrict__ out,
                                                     int out_size) {
    const int tok = blockIdx.x;
    const int ch  = threadIdx.x;
    const int bb  = tok >> 10;
    const int hw  = tok & (HW - 1);
    const size_t zoff = (size_t)bb * CDIM * HW + (size_t)ch * HW + hw;
    const float zc = z[zoff];

    // exact-rescore the 4 candidates
    int cand[4];
    #pragma unroll
    for (int i = 0; i < 4; i++)
        cand[i] = (int)(g_cand[tok * 4 + i] & 0xFFFFFFFFULL);
    float p[4];
    #pragma unroll
    for (int i = 0; i < 4; i++)
        p[i] = zc * __ldg(&g_emb[(size_t)cand[i] * CDIM + ch]);
    #pragma unroll
    for (int off = 16; off > 0; off >>= 1) {
        #pragma unroll
        for (int i = 0; i < 4; i++)
            p[i] += __shfl_xor_sync(0xFFFFFFFFu, p[i], off);
    }
    __shared__ float sp[4][8];
    const int warp = ch >> 5, lane = ch & 31;
    if (lane == 0) {
        #pragma unroll
        for (int i = 0; i < 4; i++) sp[i][warp] = p[i];
    }
    __syncthreads();
    float P[4] = {0.f, 0.f, 0.f, 0.f};
    #pragma unroll
    for (int w = 0; w < 8; w++) {
        #pragma unroll
        for (int i = 0; i < 4; i++) P[i] += sp[i][w];
    }
    unsigned long long bk = ~0ULL;
    #pragma unroll
    for (int i = 0; i < 4; i++) {
        const float s = fmaf(-2.0f, P[i], __ldg(&g_e2[cand[i]]));
        const unsigned long long key =
            ((unsigned long long)fkey(s) << 32) | (unsigned)cand[i];
        if (key < bk) bk = key;
    }
    const int idx = (int)(bk & 0xFFFFFFFFULL);

    // rotation trick
    const float ec = __ldg(&g_emb[(size_t)idx * CDIM + ch]);
    float zz = zc * zc, ze = zc * ec, ee = ec * ec;
    #pragma unroll
    for (int off = 16; off > 0; off >>= 1) {
        zz += __shfl_xor_sync(0xFFFFFFFFu, zz, off);
        ze += __shfl_xor_sync(0xFFFFFFFFu, ze, off);
        ee += __shfl_xor_sync(0xFFFFFFFFu, ee, off);
    }
    __shared__ float s_zz[8], s_ze[8], s_ee[8];
    if (lane == 0) { s_zz[warp] = zz; s_ze[warp] = ze; s_ee[warp] = ee; }
    __syncthreads();
    float ZZ = 0.f, ZE = 0.f, EE = 0.f;
    #pragma unroll
    for (int i = 0; i < 8; i++) { ZZ += s_zz[i]; ZE += s_ze[i]; EE += s_ee[i]; }

    const float ns = sqrtf(ZZ), nt = sqrtf(EE);
    const float rdns = 1.0f / (ns + EPSF), rdnt = 1.0f / (nt + EPSF);
    const float uq2 = ZZ*rdns*rdns + 2.0f*ZE*rdns*rdnt + EE*rdnt*rdnt;
    const float rdnw = 1.0f / (sqrtf(uq2) + EPSF);
    const float sw = (ZZ * rdns + ZE * rdnt) * rdnw;
    const float su = ZZ * rdns;
    const float scale = nt * rdns;

    const float u_ch = zc * rdns, q_ch = ec * rdnt;
    const float w_ch = (u_ch + q_ch) * rdnw;
    const float rot = zc - 2.0f * sw * w_ch + 2.0f * su * q_ch;
    out[zoff] = rot * scale;

    if (ch == 0) {
        if (out_size > ZQ_ELEMS) {
            const float sq = ZZ - 2.0f * ZE + EE;
            atomicAdd(&out[ZQ_ELEMS], 1.25f * sq / (float)ZQ_ELEMS);
        }
        if (out_size >= ZQ_ELEMS + 1 + NTOK)
            out[ZQ_ELEMS + 1 + tok] = (float)idx;
    }
}

extern "C" void kernel_launch(void* const* d_in, const int* in_sizes, int n_in,
                              void* d_out, int out_size) {
    const float* z  = (const float*)d_in[0];   // (8,256,32,32)
    const float* cb = (const float*)d_in[1];   // (16384,256)
    const float* W  = (const float*)d_in[2];   // (256,256)
    float* out = (float*)d_out;

    cudaFuncSetAttribute(dist_kernel,
                         cudaFuncAttributeMaxDynamicSharedMemorySize, SMEM_DYN_D);

    zsplit_kernel<<<dim3(4, NTOK / 64), 256>>>(z);
    emb_kernel<<<dim3(4, NE / 64), 256>>>(cb, W);
    e2_kernel<<<NE / 8, 256>>>(out, out_size);
    dist_kernel<<<dim3(NSPLIT2, NTOK / MTILE), 256, SMEM_DYN_D>>>(out);
    rotate_kernel<<<NTOK, 256>>>(z, out, out_size);
}

// round 4
// speedup vs baseline: 2.7212x; 1.3241x over previous
#include <cuda_runtime.h>
#include <cuda_bf16.h>
#include <cstdint>
#include <math.h>

#define NTOK 8192
#define NE   16384
#define CDIM 256
#define HW   1024
#define ZQ_ELEMS (NTOK*CDIM)
#define EPSF 1e-6f

#define NSPLIT2 2
#define MTILE 128          // tokens per CTA
#define NTILE 128          // codes per N-tile
#define NT_PER_CTA ((NE/NSPLIT2)/NTILE)   // 64 tiles
#define NCHUNK (NT_PER_CTA*4)             // 256 64-k chunks

// smem layout (dist kernel) -- separate hi/lo bf16 planes, ldmatrix-padded
//  A plane row: 256 k * 2B + 16 pad = 528 (33*16B -> 8 tile rows CF)
//  B plane row:  64 k * 2B + 16 pad = 144 ( 9*16B -> CF)
#define BROW 144u
#define AROW 528u
#define OFF_BH(buf) ((unsigned)(buf)*18432u)            // 128*144 per buf
#define OFF_BL(buf) (36864u + (unsigned)(buf)*18432u)
#define OFF_E2 73728u                                   // 2 * 512B
#define OFF_AH 74752u                                   // 128*528 = 67584
#define OFF_AL 142336u
#define SMEM_DYN_D 209920

// ---------------- device scratch (static, allocation-free) ----------------
__device__ float g_emb[NE * CDIM];            // fp32 emb = cb @ W^T
__device__ float g_e2[NE];                    // |emb_j|^2
__device__ unsigned short g_emb_h[NE * CDIM]; // bf16 hi plane
__device__ unsigned short g_emb_l[NE * CDIM]; // bf16 lo plane
__device__ unsigned short g_z_h[NTOK * CDIM];
__device__ unsigned short g_z_l[NTOK * CDIM];
__device__ unsigned long long g_cand[NTOK * 4];  // best-2 per (tok, split)

// ---------------- helpers --------------------------------------------------
__device__ __forceinline__ uint32_t smem_u32(const void* p) {
    uint32_t a;
    asm("{ .reg .u64 t; cvta.to.shared.u64 t, %1; cvt.u32.u64 %0, t; }"
        : "=r"(a) : "l"(p));
    return a;
}
__device__ __forceinline__ void cp16(uint32_t dst, const void* src) {
    asm volatile("cp.async.cg.shared.global [%0], [%1], 16;" :: "r"(dst), "l"(src));
}
__device__ __forceinline__ void cp_commit() { asm volatile("cp.async.commit_group;"); }
__device__ __forceinline__ void cp_wait0()  { asm volatile("cp.async.wait_group 0;"); }
#define LDSM4(r0,r1,r2,r3,addr) \
    asm volatile("ldmatrix.sync.aligned.m8n8.x4.shared.b16 {%0,%1,%2,%3}, [%4];" \
        : "=r"(r0), "=r"(r1), "=r"(r2), "=r"(r3) : "r"(addr))
__device__ __forceinline__ void mma16816(float* c, const uint32_t* a,
                                         uint32_t b0, uint32_t b1) {
    asm volatile(
        "mma.sync.aligned.m16n8k16.row.col.f32.bf16.bf16.f32 "
        "{%0,%1,%2,%3}, {%4,%5,%6,%7}, {%8,%9}, {%0,%1,%2,%3};"
        : "+f"(c[0]), "+f"(c[1]), "+f"(c[2]), "+f"(c[3])
        : "r"(a[0]), "r"(a[1]), "r"(a[2]), "r"(a[3]), "r"(b0), "r"(b1));
}
__device__ __forceinline__ unsigned int fkey(float f) {
    unsigned int u = __float_as_uint(f);
    return (u & 0x80000000u) ? ~u : (u | 0x80000000u);
}
__device__ __forceinline__ unsigned short bfu(__nv_bfloat16 h) {
    return __bfloat16_as_ushort(h);
}
__device__ __forceinline__ void best2_upd(unsigned long long& b1,
                                          unsigned long long& b2,
                                          unsigned long long k) {
    if (k < b1) { b2 = b1; b1 = k; } else if (k < b2) { b2 = k; }
}

// ---------------------------------------------------------------------------
// z split: fp32 z -> separate bf16 hi/lo planes, token-major rows.
// ---------------------------------------------------------------------------
__global__ __launch_bounds__(256) void zsplit_kernel(const float* __restrict__ z) {
    __shared__ float s[64][65];
    const int tid = threadIdx.x;
    const int t0 = blockIdx.y * 64;
    const int p0 = blockIdx.x * 32;     // k-pair block (32 pairs = 64 k)
    const int bb = t0 >> 10;
    const int hw0 = t0 & (HW - 1);
    const float* zb = z + (size_t)bb * CDIM * HW + hw0;

    #pragma unroll
    for (int r = 0; r < 16; r++) {
        const int id = tid + 256 * r;
        const int kk = id >> 6, tt = id & 63;
        s[kk][tt] = zb[(size_t)(2 * p0 + kk) * HW + tt];
    }
    __syncthreads();
    #pragma unroll
    for (int r = 0; r < 8; r++) {
        const int id = tid + 256 * r;
        const int tt = id >> 5, pp = id & 31;
        const float z0 = s[2 * pp][tt], z1 = s[2 * pp + 1][tt];
        const __nv_bfloat16 h0 = __float2bfloat16(z0), h1 = __float2bfloat16(z1);
        const __nv_bfloat16 l0 = __float2bfloat16(z0 - __bfloat162float(h0));
        const __nv_bfloat16 l1 = __float2bfloat16(z1 - __bfloat162float(h1));
        const size_t o = (size_t)(t0 + tt) * 128 + p0 + pp;
        ((uint32_t*)g_z_h)[o] = (uint32_t)bfu(h0) | ((uint32_t)bfu(h1) << 16);
        ((uint32_t*)g_z_l)[o] = (uint32_t)bfu(l0) | ((uint32_t)bfu(l1) << 16);
    }
}

// ---------------------------------------------------------------------------
// emb = codebook @ W^T fp32 + bf16 hi/lo plane outputs
// ---------------------------------------------------------------------------
__global__ __launch_bounds__(256) void emb_kernel(const float* __restrict__ cb,
                                                  const float* __restrict__ W) {
    __shared__ float As[16][68];
    __shared__ float Bs[16][68];
    const int t  = threadIdx.x;
    const int tx = t & 15, ty = t >> 4;
    const int m0 = blockIdx.y * 64;
    const int n0 = blockIdx.x * 64;

    float acc[4][4] = {};
    for (int k0 = 0; k0 < CDIM; k0 += 16) {
        __syncthreads();
        const int kk = t & 15, mm = t >> 4;
        #pragma unroll
        for (int r = 0; r < 4; r++) {
            As[kk][mm + 16*r] = cb[(m0 + mm + 16*r) * CDIM + k0 + kk];
            Bs[kk][mm + 16*r] = W [(n0 + mm + 16*r) * CDIM + k0 + kk];
        }
        __syncthreads();
        #pragma unroll
        for (int k = 0; k < 16; k++) {
            float4 a = *(const float4*)&As[k][ty * 4];
            float4 b = *(const float4*)&Bs[k][tx * 4];
            float av[4] = {a.x, a.y, a.z, a.w};
            float bv[4] = {b.x, b.y, b.z, b.w};
            #pragma unroll
            for (int i = 0; i < 4; i++)
                #pragma unroll
                for (int j = 0; j < 4; j++)
                    acc[i][j] = fmaf(av[i], bv[j], acc[i][j]);
        }
    }
    #pragma unroll
    for (int i = 0; i < 4; i++) {
        const int code = m0 + ty * 4 + i;
        float4 v = make_float4(acc[i][0], acc[i][1], acc[i][2], acc[i][3]);
        const int e0 = code * CDIM + n0 + tx * 4;
        *(float4*)&g_emb[e0] = v;
        __nv_bfloat16 h0 = __float2bfloat16(v.x), h1 = __float2bfloat16(v.y);
        __nv_bfloat16 h2 = __float2bfloat16(v.z), h3 = __float2bfloat16(v.w);
        __nv_bfloat16 l0 = __float2bfloat16(v.x - __bfloat162float(h0));
        __nv_bfloat16 l1 = __float2bfloat16(v.y - __bfloat162float(h1));
        __nv_bfloat16 l2 = __float2bfloat16(v.z - __bfloat162float(h2));
        __nv_bfloat16 l3 = __float2bfloat16(v.w - __bfloat162float(h3));
        uint2 hp, lp;
        hp.x = (uint32_t)bfu(h0) | ((uint32_t)bfu(h1) << 16);
        hp.y = (uint32_t)bfu(h2) | ((uint32_t)bfu(h3) << 16);
        lp.x = (uint32_t)bfu(l0) | ((uint32_t)bfu(l1) << 16);
        lp.y = (uint32_t)bfu(l2) | ((uint32_t)bfu(l3) << 16);
        ((uint2*)g_emb_h)[e0 >> 2] = hp;
        ((uint2*)g_emb_l)[e0 >> 2] = lp;
    }
}

// deterministic e2 + loss-slot init
__global__ __launch_bounds__(256) void e2_kernel(float* out, int out_size) {
    const int code = blockIdx.x * 8 + (threadIdx.x >> 5);
    const int lane = threadIdx.x & 31;
    const float* row = g_emb + (size_t)code * CDIM;
    float s = 0.0f;
    #pragma unroll
    for (int i = 0; i < 8; i++) { float v = row[lane + 32*i]; s = fmaf(v, v, s); }
    #pragma unroll
    for (int off = 16; off > 0; off >>= 1) s += __shfl_xor_sync(0xFFFFFFFFu, s, off);
    if (lane == 0) g_e2[code] = s;
    if (blockIdx.x == 0 && threadIdx.x == 0 && out_size > ZQ_ELEMS) out[ZQ_ELEMS] = 0.0f;
}

// ---------------------------------------------------------------------------
// Distance GEMM (split-bf16 3-pass HMMA + ldmatrix) + best-2 per (tok,split).
// CTA tile 128x128, 8 warps = 4(M) x 2(N), warp tile 32x64.
// ---------------------------------------------------------------------------
__global__ __launch_bounds__(256, 1) void dist_kernel(float* dummy) {
    extern __shared__ char smem[];
    const uint32_t sb = smem_u32(smem);
    const int tid  = threadIdx.x;
    const int lane = tid & 31, wid = tid >> 5;
    const int gid  = lane >> 2, tig = lane & 3;
    const int wm = wid & 3, wn = wid >> 2;
    const int m_base = wm * 32, n_base = wn * 64;
    const int m0 = blockIdx.y * MTILE;
    const int nbase = blockIdx.x * (NE / NSPLIT2);

    // ---- prologue staging: A planes (full K) + B chunk 0 + e2 tile 0 ----
    {
        const unsigned short* zh = g_z_h + (size_t)m0 * CDIM;
        const unsigned short* zl = g_z_l + (size_t)m0 * CDIM;
        #pragma unroll
        for (int r = 0; r < 16; r++) {
            const int id = tid + 256 * r;
            const int ml = id >> 5, cj = id & 31;
            cp16(sb + OFF_AH + (unsigned)ml * AROW + (unsigned)cj * 16u, zh + ml * 256 + cj * 8);
            cp16(sb + OFF_AL + (unsigned)ml * AROW + (unsigned)cj * 16u, zl + ml * 256 + cj * 8);
        }
        #pragma unroll
        for (int r = 0; r < 4; r++) {
            const int id = tid + 256 * r;
            const int nl = id >> 3, cj = id & 7;
            cp16(sb + OFF_BH(0) + (unsigned)nl * BROW + (unsigned)cj * 16u,
                 g_emb_h + (size_t)(nbase + nl) * 256 + cj * 8);
            cp16(sb + OFF_BL(0) + (unsigned)nl * BROW + (unsigned)cj * 16u,
                 g_emb_l + (size_t)(nbase + nl) * 256 + cj * 8);
        }
        if (tid < 32) cp16(sb + OFF_E2 + (unsigned)tid * 16u, g_e2 + nbase + tid * 4);
        cp_commit(); cp_wait0(); __syncthreads();
    }

    // lane-invariant ldmatrix base offsets
    const uint32_t aoffA = (uint32_t)((m_base + ((lane >> 3) & 1) * 8 + (lane & 7)) * AROW
                                      + ((lane >> 4) * 8) * 2);
    const uint32_t aAh = sb + OFF_AH + aoffA;
    const uint32_t aAl = sb + OFF_AL + aoffA;
    const uint32_t boffB = (uint32_t)((n_base + (lane >> 4) * 8 + (lane & 7)) * BROW
                                      + (((lane >> 3) & 1) * 8) * 2);

    unsigned long long b1[4] = {~0ULL, ~0ULL, ~0ULL, ~0ULL};
    unsigned long long b2[4] = {~0ULL, ~0ULL, ~0ULL, ~0ULL};

    int q = 0;
    for (int nt = 0; nt < NT_PER_CTA; nt++) {
        float acc[2][8][4] = {};
        #pragma unroll 1
        for (int kc = 0; kc < 4; kc++, q++) {
            const int qn = q + 1;
            if (qn < NCHUNK) {
                const int nt2 = qn >> 2, kc2 = qn & 3;
                const int n2 = nbase + nt2 * NTILE;
                #pragma unroll
                for (int r = 0; r < 4; r++) {
                    const int id = tid + 256 * r;
                    const int nl = id >> 3, cj = id & 7;
                    cp16(sb + OFF_BH(qn & 1) + (unsigned)nl * BROW + (unsigned)cj * 16u,
                         g_emb_h + (size_t)(n2 + nl) * 256 + kc2 * 64 + cj * 8);
                    cp16(sb + OFF_BL(qn & 1) + (unsigned)nl * BROW + (unsigned)cj * 16u,
                         g_emb_l + (size_t)(n2 + nl) * 256 + kc2 * 64 + cj * 8);
                }
                if (kc2 == 0 && tid < 32)
                    cp16(sb + OFF_E2 + ((unsigned)(nt2 & 1)) * 512u + (unsigned)tid * 16u,
                         g_e2 + n2 + tid * 4);
            }
            cp_commit();

            const uint32_t Bh = sb + OFF_BH(q & 1) + boffB;
            const uint32_t Bl = sb + OFF_BL(q & 1) + boffB;
            const uint32_t akc = (uint32_t)(kc * 128);   // 64 k-elems * 2B
            #pragma unroll
            for (int s = 0; s < 4; s++) {
                uint32_t ah[2][4], al[2][4], bh[4][4], bl[4][4];
                #pragma unroll
                for (int ma = 0; ma < 2; ma++) {
                    const uint32_t ao = akc + (uint32_t)(ma * 16) * AROW + (uint32_t)(s * 32);
                    LDSM4(ah[ma][0], ah[ma][1], ah[ma][2], ah[ma][3], aAh + ao);
                    LDSM4(al[ma][0], al[ma][1], al[ma][2], al[ma][3], aAl + ao);
                }
                #pragma unroll
                for (int nb = 0; nb < 4; nb++) {
                    const uint32_t bo = (uint32_t)(nb * 16) * BROW + (uint32_t)(s * 32);
                    LDSM4(bh[nb][0], bh[nb][1], bh[nb][2], bh[nb][3], Bh + bo);
                    LDSM4(bl[nb][0], bl[nb][1], bl[nb][2], bl[nb][3], Bl + bo);
                }
                // pass 1: zh*eh (16 independent HMMAs)
                #pragma unroll
                for (int nb = 0; nb < 4; nb++)
                    #pragma unroll
                    for (int h = 0; h < 2; h++)
                        #pragma unroll
                        for (int ma = 0; ma < 2; ma++)
                            mma16816(acc[ma][nb*2+h], ah[ma], bh[nb][2*h], bh[nb][2*h+1]);
                // pass 2: zl*eh
                #pragma unroll
                for (int nb = 0; nb < 4; nb++)
                    #pragma unroll
                    for (int h = 0; h < 2; h++)
                        #pragma unroll
                        for (int ma = 0; ma < 2; ma++)
                            mma16816(acc[ma][nb*2+h], al[ma], bh[nb][2*h], bh[nb][2*h+1]);
                // pass 3: zh*el
                #pragma unroll
                for (int nb = 0; nb < 4; nb++)
                    #pragma unroll
                    for (int h = 0; h < 2; h++)
                        #pragma unroll
                        for (int ma = 0; ma < 2; ma++)
                            mma16816(acc[ma][nb*2+h], ah[ma], bl[nb][2*h], bl[nb][2*h+1]);
            }
            cp_wait0();
            __syncthreads();
        }
        // ---- epilogue: scores + best-2 ----
        const float* e2p = (const float*)(smem + OFF_E2 + (size_t)(nt & 1) * 512);
        const int n0 = nbase + nt * NTILE;
        #pragma unroll
        for (int na = 0; na < 8; na++) {
            const int c0 = n_base + na * 8 + tig * 2;
            const float e2a = e2p[c0], e2b = e2p[c0 + 1];
            #pragma unroll
            for (int ma = 0; ma < 2; ma++) {
                const float s00 = fmaf(-2.0f, acc[ma][na][0], e2a);
                const float s01 = fmaf(-2.0f, acc[ma][na][1], e2b);
                const float s10 = fmaf(-2.0f, acc[ma][na][2], e2a);
                const float s11 = fmaf(-2.0f, acc[ma][na][3], e2b);
                const int q0 = ma * 2;
                best2_upd(b1[q0], b2[q0],
                    ((unsigned long long)fkey(s00) << 32) | (unsigned)(n0 + c0));
                best2_upd(b1[q0], b2[q0],
                    ((unsigned long long)fkey(s01) << 32) | (unsigned)(n0 + c0 + 1));
                best2_upd(b1[q0 + 1], b2[q0 + 1],
                    ((unsigned long long)fkey(s10) << 32) | (unsigned)(n0 + c0));
                best2_upd(b1[q0 + 1], b2[q0 + 1],
                    ((unsigned long long)fkey(s11) << 32) | (unsigned)(n0 + c0 + 1));
            }
        }
    }

    // ---- CTA reduction ----
    __syncthreads();
    unsigned long long* red = (unsigned long long*)smem;  // 128 rows x 2 wn x 2
    #pragma unroll
    for (int qq = 0; qq < 4; qq++) {
        unsigned long long k1 = b1[qq], k2 = b2[qq];
        #pragma unroll
        for (int off = 1; off <= 2; off <<= 1) {
            unsigned long long o1 = __shfl_xor_sync(0xFFFFFFFFu, k1, off);
            unsigned long long o2 = __shfl_xor_sync(0xFFFFFFFFu, k2, off);
            unsigned long long n1 = k1 < o1 ? k1 : o1;
            unsigned long long hi = k1 < o1 ? o1 : k1;
            unsigned long long lo2 = k2 < o2 ? k2 : o2;
            k1 = n1;
            k2 = hi < lo2 ? hi : lo2;
        }
        if (tig == 0) {
            const int row = m_base + (qq >> 1) * 16 + gid + (qq & 1) * 8;
            red[(row * 2 + wn) * 2 + 0] = k1;
            red[(row * 2 + wn) * 2 + 1] = k2;
        }
    }
    __syncthreads();
    if (tid < 128) {
        unsigned long long a1 = red[tid * 4 + 0], a2 = red[tid * 4 + 1];
        unsigned long long c1 = red[tid * 4 + 2], c2 = red[tid * 4 + 3];
        unsigned long long k1 = a1 < c1 ? a1 : c1;
        unsigned long long hi = a1 < c1 ? c1 : a1;
        unsigned long long lo2 = a2 < c2 ? a2 : c2;
        unsigned long long k2 = hi < lo2 ? hi : lo2;
        g_cand[(size_t)(m0 + tid) * 4 + blockIdx.x * 2 + 0] = k1;
        g_cand[(size_t)(m0 + tid) * 4 + blockIdx.x * 2 + 1] = k2;
    }
}

// ---------------------------------------------------------------------------
// Candidate refine (exact fp32) + rotation trick + loss + indices.
// ---------------------------------------------------------------------------
__global__ __launch_bounds__(256) void rotate_kernel(const float* __restrict__ z,
                                                     float* __restrict__ out,
                                                     int out_size) {
    const int tok = blockIdx.x;
    const int ch  = threadIdx.x;
    const int bb  = tok >> 10;
    const int hw  = tok & (HW - 1);
    const size_t zoff = (size_t)bb * CDIM * HW + (size_t)ch * HW + hw;
    const float zc = z[zoff];

    int cand[4];
    #pragma unroll
    for (int i = 0; i < 4; i++)
        cand[i] = (int)(g_cand[tok * 4 + i] & 0xFFFFFFFFULL);
    float p[4];
    #pragma unroll
    for (int i = 0; i < 4; i++)
        p[i] = zc * __ldg(&g_emb[(size_t)cand[i] * CDIM + ch]);
    #pragma unroll
    for (int off = 16; off > 0; off >>= 1) {
        #pragma unroll
        for (int i = 0; i < 4; i++)
            p[i] += __shfl_xor_sync(0xFFFFFFFFu, p[i], off);
    }
    __shared__ float sp[4][8];
    const int warp = ch >> 5, lane = ch & 31;
    if (lane == 0) {
        #pragma unroll
        for (int i = 0; i < 4; i++) sp[i][warp] = p[i];
    }
    __syncthreads();
    float P[4] = {0.f, 0.f, 0.f, 0.f};
    #pragma unroll
    for (int w = 0; w < 8; w++) {
        #pragma unroll
        for (int i = 0; i < 4; i++) P[i] += sp[i][w];
    }
    unsigned long long bk = ~0ULL;
    #pragma unroll
    for (int i = 0; i < 4; i++) {
        const float s = fmaf(-2.0f, P[i], __ldg(&g_e2[cand[i]]));
        const unsigned long long key =
            ((unsigned long long)fkey(s) << 32) | (unsigned)cand[i];
        if (key < bk) bk = key;
    }
    const int idx = (int)(bk & 0xFFFFFFFFULL);

    const float ec = __ldg(&g_emb[(size_t)idx * CDIM + ch]);
    float zz = zc * zc, ze = zc * ec, ee = ec * ec;
    #pragma unroll
    for (int off = 16; off > 0; off >>= 1) {
        zz += __shfl_xor_sync(0xFFFFFFFFu, zz, off);
        ze += __shfl_xor_sync(0xFFFFFFFFu, ze, off);
        ee += __shfl_xor_sync(0xFFFFFFFFu, ee, off);
    }
    __shared__ float s_zz[8], s_ze[8], s_ee[8];
    if (lane == 0) { s_zz[warp] = zz; s_ze[warp] = ze; s_ee[warp] = ee; }
    __syncthreads();
    float ZZ = 0.f, ZE = 0.f, EE = 0.f;
    #pragma unroll
    for (int i = 0; i < 8; i++) { ZZ += s_zz[i]; ZE += s_ze[i]; EE += s_ee[i]; }

    const float ns = sqrtf(ZZ), nt = sqrtf(EE);
    const float rdns = 1.0f / (ns + EPSF), rdnt = 1.0f / (nt + EPSF);
    const float uq2 = ZZ*rdns*rdns + 2.0f*ZE*rdns*rdnt + EE*rdnt*rdnt;
    const float rdnw = 1.0f / (sqrtf(uq2) + EPSF);
    const float sw = (ZZ * rdns + ZE * rdnt) * rdnw;
    const float su = ZZ * rdns;
    const float scale = nt * rdns;

    const float u_ch = zc * rdns, q_ch = ec * rdnt;
    const float w_ch = (u_ch + q_ch) * rdnw;
    const float rot = zc - 2.0f * sw * w_ch + 2.0f * su * q_ch;
    out[zoff] = rot * scale;

    if (ch == 0) {
        if (out_size > ZQ_ELEMS) {
            const float sq = ZZ - 2.0f * ZE + EE;
            atomicAdd(&out[ZQ_ELEMS], 1.25f * sq / (float)ZQ_ELEMS);
        }
        if (out_size >= ZQ_ELEMS + 1 + NTOK)
            out[ZQ_ELEMS + 1 + tok] = (float)idx;
    }
}

extern "C" void kernel_launch(void* const* d_in, const int* in_sizes, int n_in,
                              void* d_out, int out_size) {
    const float* z  = (const float*)d_in[0];   // (8,256,32,32)
    const float* cb = (const float*)d_in[1];   // (16384,256)
    const float* W  = (const float*)d_in[2];   // (256,256)
    float* out = (float*)d_out;

    cudaFuncSetAttribute(dist_kernel,
                         cudaFuncAttributeMaxDynamicSharedMemorySize, SMEM_DYN_D);

    zsplit_kernel<<<dim3(4, NTOK / 64), 256>>>(z);
    emb_kernel<<<dim3(4, NE / 64), 256>>>(cb, W);
    e2_kernel<<<NE / 8, 256>>>(out, out_size);
    dist_kernel<<<dim3(NSPLIT2, NTOK / MTILE), 256, SMEM_DYN_D>>>(out);
    rotate_kernel<<<NTOK, 256>>>(z, out, out_size);
}